// round 1
// baseline (speedup 1.0000x reference)
#include <cuda_runtime.h>

// Problem constants
#define N_ROWS   32768     // B*H*W = 32*32*32
#define D_DIM    256
#define K_CODES  1024
#define OUT_ELEMS 8388608  // N_ROWS * D_DIM

// ---------------- device scratch (no allocations allowed) ----------------
__device__ float g_wsq[K_CODES];                 // ||e_k||^2
__device__ float g_wT[K_CODES * D_DIM];          // weight transposed [K][D] for coalesced gather
__device__ float g_sumz[N_ROWS];                 // ||z_n||^2
__device__ float g_pval[N_ROWS * 8];             // per-col-tile partial min value
__device__ int   g_pidx[N_ROWS * 8];             // per-col-tile partial argmin
__device__ int   g_closest[N_ROWS];              // final argmin
__device__ float g_partial[8192];                // loss partials (1024 x 8 scatter blocks)

// ---------------- kernel 1: wsq[k] = sum_d w[d][k]^2 ----------------
__global__ void wsq_kernel(const float* __restrict__ w) {
    int k = blockIdx.x * 256 + threadIdx.x;   // grid 4 x 256
    float s = 0.f;
    #pragma unroll 8
    for (int d = 0; d < D_DIM; d++) {
        float v = w[d * K_CODES + k];
        s = fmaf(v, v, s);
    }
    g_wsq[k] = s;
}

// ---------------- kernel 2: wT[k][d] = w[d][k] ----------------
__global__ void transpose_kernel(const float* __restrict__ w) {
    __shared__ float t[32][33];
    int k0 = blockIdx.x * 32, d0 = blockIdx.y * 32;   // grid (32, 8), block (32, 8)
    int x = threadIdx.x, y = threadIdx.y;
    #pragma unroll
    for (int i = 0; i < 32; i += 8)
        t[y + i][x] = w[(d0 + y + i) * K_CODES + k0 + x];
    __syncthreads();
    #pragma unroll
    for (int i = 0; i < 32; i += 8)
        g_wT[(k0 + y + i) * D_DIM + d0 + x] = t[x][y + i];
}

// ---------------- kernel 3: sumz[n] = sum_d z[n][d]^2 ----------------
__global__ void sumz_kernel(const float* __restrict__ z) {
    int warp = threadIdx.x >> 5, lane = threadIdx.x & 31;
    int row = blockIdx.x * 8 + warp;          // grid 4096 x 256
    const float* zr = z + (size_t)row * D_DIM;
    float s = 0.f;
    #pragma unroll
    for (int j = 0; j < D_DIM / 32; j++) {
        float v = zr[lane + 32 * j];
        s = fmaf(v, v, s);
    }
    #pragma unroll
    for (int o = 16; o > 0; o >>= 1)
        s += __shfl_down_sync(0xffffffffu, s, o);
    if (lane == 0) g_sumz[row] = s;
}

// ---------------- kernel 4: distance GEMM + per-tile argmin ----------------
// grid (256 row-tiles, 8 col-tiles), 256 threads. Tile: 128 rows x 128 cols, BK=32.
__global__ void __launch_bounds__(256) dist_argmin_kernel(
    const float* __restrict__ z, const float* __restrict__ w)
{
    __shared__ float As[32][132];   // [dk][m], transposed, padded
    __shared__ float Bs[32][128];   // [dk][k]

    const int n0 = blockIdx.x * 128;
    const int k0 = blockIdx.y * 128;
    const int tid = threadIdx.x;
    const int tx = tid & 15, ty = tid >> 4;

    float acc[8][8];
    #pragma unroll
    for (int i = 0; i < 8; i++)
        #pragma unroll
        for (int j = 0; j < 8; j++) acc[i][j] = 0.f;

    for (int dt = 0; dt < D_DIM; dt += 32) {
        // load A tile: 128 rows x 32 d  (transpose into As)
        #pragma unroll
        for (int i = 0; i < 4; i++) {
            int idx = tid + 256 * i;
            int r = idx >> 3, c4 = idx & 7;
            float4 v = *reinterpret_cast<const float4*>(z + (size_t)(n0 + r) * D_DIM + dt + c4 * 4);
            As[c4 * 4 + 0][r] = v.x;
            As[c4 * 4 + 1][r] = v.y;
            As[c4 * 4 + 2][r] = v.z;
            As[c4 * 4 + 3][r] = v.w;
        }
        // load B tile: 32 d x 128 k
        #pragma unroll
        for (int i = 0; i < 4; i++) {
            int idx = tid + 256 * i;
            int row = idx >> 5, c4 = idx & 31;
            float4 v = *reinterpret_cast<const float4*>(w + (size_t)(dt + row) * K_CODES + k0 + c4 * 4);
            *reinterpret_cast<float4*>(&Bs[row][c4 * 4]) = v;
        }
        __syncthreads();

        #pragma unroll 8
        for (int kk = 0; kk < 32; kk++) {
            const float4* Ar = reinterpret_cast<const float4*>(&As[kk][0]);
            const float4* Br = reinterpret_cast<const float4*>(&Bs[kk][0]);
            float4 a0 = Ar[ty], a1 = Ar[ty + 16];
            float4 b0 = Br[tx], b1 = Br[tx + 16];
            float av[8] = {a0.x, a0.y, a0.z, a0.w, a1.x, a1.y, a1.z, a1.w};
            float bv[8] = {b0.x, b0.y, b0.z, b0.w, b1.x, b1.y, b1.z, b1.w};
            #pragma unroll
            for (int i = 0; i < 8; i++)
                #pragma unroll
                for (int j = 0; j < 8; j++)
                    acc[i][j] = fmaf(av[i], bv[j], acc[i][j]);
        }
        __syncthreads();
    }

    // epilogue: dist = fl(sumz + wsq) - 2*dot  (single-rounding FFMA matches ref)
    float sz[8], wq[8];
    int rows[8], cols[8];
    #pragma unroll
    for (int i = 0; i < 8; i++) {
        rows[i] = (i < 4) ? (ty * 4 + i) : (64 + ty * 4 + i - 4);
        cols[i] = (i < 4) ? (tx * 4 + i) : (64 + tx * 4 + i - 4);
        sz[i] = g_sumz[n0 + rows[i]];
        wq[i] = g_wsq[k0 + cols[i]];
    }

    // reuse shared memory for the cross-thread reduction
    float* svals = &Bs[0][0];           // 128 x 16
    int*   sidxs = reinterpret_cast<int*>(&As[0][0]);

    #pragma unroll
    for (int i = 0; i < 8; i++) {
        float bestv; int besti;
        #pragma unroll
        for (int j = 0; j < 8; j++) {   // cols[j] ascending -> strict < keeps first index
            float t = sz[i] + wq[j];
            float dist = fmaf(-2.0f, acc[i][j], t);
            if (j == 0 || dist < bestv) { bestv = dist; besti = k0 + cols[j]; }
        }
        svals[rows[i] * 16 + tx] = bestv;
        sidxs[rows[i] * 16 + tx] = besti;
    }
    __syncthreads();

    if (tid < 128) {
        float bestv = svals[tid * 16];
        int   besti = sidxs[tid * 16];
        #pragma unroll
        for (int t = 1; t < 16; t++) {
            float v = svals[tid * 16 + t];
            int   id = sidxs[tid * 16 + t];
            if (v < bestv || (v == bestv && id < besti)) { bestv = v; besti = id; }
        }
        g_pval[(size_t)(n0 + tid) * 8 + blockIdx.y] = bestv;
        g_pidx[(size_t)(n0 + tid) * 8 + blockIdx.y] = besti;
    }
}

// ---------------- kernel 5: combine partial argmins ----------------
__global__ void combine_kernel() {
    int n = blockIdx.x * 256 + threadIdx.x;   // grid 128 x 256
    float bestv = g_pval[(size_t)n * 8];
    int   besti = g_pidx[(size_t)n * 8];
    #pragma unroll
    for (int t = 1; t < 8; t++) {             // later tiles have strictly larger indices
        float v = g_pval[(size_t)n * 8 + t];
        int  id = g_pidx[(size_t)n * 8 + t];
        if (v < bestv || (v == bestv && id < besti)) { bestv = v; besti = id; }
    }
    g_closest[n] = besti;
}

// ---------------- kernel 6: gather + transpose write + loss partials ----------------
// grid (1024 n-blocks, 8 d-blocks), 256 threads; 32x32 tile
__global__ void scatter_kernel(const float* __restrict__ z, float* __restrict__ out) {
    __shared__ int   sidx[32];
    __shared__ float tile[32][33];
    __shared__ float red[256];

    int n0 = blockIdx.x * 32, d0 = blockIdx.y * 32;
    int tid = threadIdx.x, warp = tid >> 5, lane = tid & 31;

    if (tid < 32) sidx[tid] = g_closest[n0 + tid];
    __syncthreads();

    float part = 0.f;
    #pragma unroll
    for (int it = 0; it < 4; it++) {
        int ni = it * 8 + warp;
        int n = n0 + ni;
        float zv = z[(size_t)n * D_DIM + d0 + lane];
        float q = g_wT[(size_t)sidx[ni] * D_DIM + d0 + lane];   // coalesced gather
        float d = q - zv;
        part = fmaf(d, d, part);
        tile[lane][ni] = q;    // tile[d_local][n_local]
    }
    __syncthreads();

    // write out[b][d][h][w]; n0 aligned to 32 -> fixed (b, h), lane = w
    int b = n0 >> 10;
    int hwbase = n0 & 1023;
    #pragma unroll
    for (int it = 0; it < 4; it++) {
        int dl = it * 8 + warp;
        out[(size_t)b * 262144 + (size_t)(d0 + dl) * 1024 + hwbase + lane] = tile[dl][lane];
    }

    // deterministic block reduction for the loss
    red[tid] = part;
    __syncthreads();
    #pragma unroll
    for (int s = 128; s > 0; s >>= 1) {
        if (tid < s) red[tid] += red[tid + s];
        __syncthreads();
    }
    if (tid == 0) g_partial[blockIdx.y * 1024 + blockIdx.x] = red[0];
}

// ---------------- kernel 7: finalize losses (deterministic) ----------------
__global__ void finalize_kernel(float* __restrict__ out, int out_size) {
    __shared__ double sdata[256];
    int tid = threadIdx.x;
    double s = 0.0;
    for (int i = tid * 32; i < tid * 32 + 32; i++) s += (double)g_partial[i];
    sdata[tid] = s;
    __syncthreads();
    #pragma unroll
    for (int st = 128; st > 0; st >>= 1) {
        if (tid < st) sdata[tid] += sdata[tid + st];
        __syncthreads();
    }
    if (tid == 0) {
        float loss = (float)(sdata[0] / (double)OUT_ELEMS);
        out[out_size - 2] = loss;   // commitment_loss
        out[out_size - 1] = loss;   // embedding_loss (identical value)
    }
}

// ---------------- launcher ----------------
extern "C" void kernel_launch(void* const* d_in, const int* in_sizes, int n_in,
                              void* d_out, int out_size) {
    (void)in_sizes; (void)n_in;
    const float* z = (const float*)d_in[0];       // [32768, 256]
    const float* w = (const float*)d_in[1];       // [256, 1024]
    float* out = (float*)d_out;

    wsq_kernel<<<K_CODES / 256, 256>>>(w);
    transpose_kernel<<<dim3(K_CODES / 32, D_DIM / 32), dim3(32, 8)>>>(w);
    sumz_kernel<<<N_ROWS / 8, 256>>>(z);
    dist_argmin_kernel<<<dim3(N_ROWS / 128, K_CODES / 128), 256>>>(z, w);
    combine_kernel<<<N_ROWS / 256, 256>>>();
    scatter_kernel<<<dim3(N_ROWS / 32, D_DIM / 32), 256>>>(z, out);
    finalize_kernel<<<1, 256>>>(out, out_size);
}

// round 4
// speedup vs baseline: 1.4430x; 1.4430x over previous
#include <cuda_runtime.h>
#include <cuda_fp16.h>
#include <cstdint>

#define N_ROWS   32768
#define D_DIM    256
#define K_CODES  1024
#define OUT_ELEMS 8388608
#define MARGIN   4e-3f

// ---------------- device scratch ----------------
__device__ float  g_wsq[K_CODES];
__device__ float  g_wT[K_CODES * D_DIM];         // exact fp32 transpose (rescore + gather)
__device__ float  g_wBpk[8][8][4096];            // tf32 prepacked SMEM image [codeTile][dChunk]
__device__ float  g_sumz[N_ROWS];
__device__ float  g_pval[N_ROWS * 8];            // per-col-tile screen min
__device__ float  g_cmin[N_ROWS];
__device__ __half g_scr[(size_t)N_ROWS * K_CODES]; // 64MB screen values c = wsq - 2*dot
__device__ int    g_closest[N_ROWS];
__device__ float  g_partial[8192];

// ---------------- helpers ----------------
__device__ __forceinline__ uint32_t smem_u32(const void* p) {
    uint32_t a;
    asm("{ .reg .u64 t; cvta.to.shared.u64 t, %1; cvt.u32.u64 %0, t; }" : "=r"(a) : "l"(p));
    return a;
}
// FIX: tf32 cvt destination must be a .b32 register, not .f32
__device__ __forceinline__ float tf32_rna(float x) {
    uint32_t r;
    asm("cvt.rna.tf32.f32 %0, %1;" : "=r"(r) : "f"(x));
    return __uint_as_float(r);
}
__device__ __forceinline__ void cpasync16(uint32_t dst, const float* src) {
    asm volatile("cp.async.cg.shared.global [%0], [%1], 16;" :: "r"(dst), "l"(src));
}
__device__ __forceinline__ void mma_tf32(float* c, uint32_t a0, uint32_t a1, uint32_t a2, uint32_t a3,
                                         uint32_t b0, uint32_t b1) {
    asm volatile(
        "mma.sync.aligned.m16n8k8.row.col.f32.tf32.tf32.f32 "
        "{%0,%1,%2,%3}, {%4,%5,%6,%7}, {%8,%9}, {%0,%1,%2,%3};"
        : "+f"(c[0]), "+f"(c[1]), "+f"(c[2]), "+f"(c[3])
        : "r"(a0), "r"(a1), "r"(a2), "r"(a3), "r"(b0), "r"(b1));
}

// ---------------- kernel 1: wsq ----------------
__global__ void wsq_kernel(const float* __restrict__ w) {
    int k = blockIdx.x * 256 + threadIdx.x;
    float s = 0.f;
    #pragma unroll 8
    for (int d = 0; d < D_DIM; d++) {
        float v = w[d * K_CODES + k];
        s = fmaf(v, v, s);
    }
    g_wsq[k] = s;
}

// ---------------- kernel 2: transpose + tf32 prepack of w ----------------
// Prepack per (codeTile ct, dChunk ch): float2 pairs {B[k][n], B[k+4][n]}
// (k = d&31, n = code&127), float2 idx = (((n>>3)*4 + (k>>3))*8 + (n&7))*4 + (k&3)
__global__ void splitw_kernel(const float* __restrict__ w) {
    __shared__ float t[32][33];
    int k0 = blockIdx.x * 32, d0 = blockIdx.y * 32;   // grid (32, 8), block (32, 8)
    int x = threadIdx.x, y = threadIdx.y;
    #pragma unroll
    for (int i = 0; i < 32; i += 8)
        t[y + i][x] = w[(d0 + y + i) * K_CODES + k0 + x];
    __syncthreads();
    #pragma unroll
    for (int i = 0; i < 32; i += 8) {
        float v = t[x][y + i];
        int code = k0 + y + i, d = d0 + x;
        g_wT[code * D_DIM + d] = v;
        int ct = code >> 7, n = code & 127, ch = d >> 5, kk = d & 31;
        int kg = kk >> 3, tig = kk & 3, half = (kk >> 2) & 1;
        int lin = (((n >> 3) * 4 + kg) * 8 + (n & 7)) * 4 + tig;
        g_wBpk[ct][ch][lin * 2 + half] = tf32_rna(v);
    }
}

// ---------------- kernel 3: sumz ----------------
__global__ void sumz_kernel(const float* __restrict__ z) {
    int warp = threadIdx.x >> 5, lane = threadIdx.x & 31;
    int row = blockIdx.x * 8 + warp;
    const float* zr = z + (size_t)row * D_DIM;
    float s = 0.f;
    #pragma unroll
    for (int j = 0; j < D_DIM / 32; j++) {
        float v = zr[lane + 32 * j];
        s = fmaf(v, v, s);
    }
    #pragma unroll
    for (int o = 16; o > 0; o >>= 1)
        s += __shfl_down_sync(0xffffffffu, s, o);
    if (lane == 0) g_sumz[row] = s;
}

// ---------------- kernel 4: tf32 mma.sync screen GEMM ----------------
// grid (256, 8), 256 threads = 8 warps (2 m x 4 n), warp tile 64x32, BK=32, double buffered.
#define SCR_SMEM 67584

__global__ void __launch_bounds__(256) screen_kernel(const float* __restrict__ z) {
    extern __shared__ char sm[];
    const uint32_t sb = smem_u32(sm);
    const int tid = threadIdx.x, wid = tid >> 5, lane = tid & 31;
    const int g = lane >> 2, tig = lane & 3;
    const int n0 = blockIdx.x * 128, c0 = blockIdx.y * 128;
    const int wm = wid & 1;            // m half (x64)
    const int wn = wid >> 1;           // n slab (x32)

    float C[4][4][4];
    #pragma unroll
    for (int m = 0; m < 4; m++)
        #pragma unroll
        for (int j = 0; j < 4; j++)
            #pragma unroll
            for (int q = 0; q < 4; q++) C[m][j][q] = 0.f;

    const int lr = tid >> 1, lkh = tid & 1;
    const float* zsrc = z + (size_t)(n0 + lr) * D_DIM + lkh * 16;
    const int Ab = lr >> 4, Ag = lr & 7, Ahalf = (lr >> 3) & 1;

    float4 va[4];
    #pragma unroll
    for (int c = 0; c < 4; c++)
        va[c] = *reinterpret_cast<const float4*>(zsrc + c * 4);

    auto fill = [&](int ch, int s, float4* v) {
        float* A = reinterpret_cast<float*>(sm + s * 32768);
        #pragma unroll
        for (int c = 0; c < 4; c++) {
            float vs[4] = {v[c].x, v[c].y, v[c].z, v[c].w};
            #pragma unroll
            for (int e = 0; e < 4; e++) {
                int kk = lkh * 16 + c * 4 + e;
                int lin = ((Ab * 8 + (kk >> 2)) * 8 + Ag) * 4 + (kk & 3);
                A[lin * 2 + Ahalf] = tf32_rna(vs[e]);
            }
        }
        uint32_t Bdst = sb + s * 32768 + 16384;
        const float* Bsrc = &g_wBpk[blockIdx.y][ch][0];
        #pragma unroll
        for (int q = 0; q < 4; q++)
            cpasync16(Bdst + (tid + q * 256) * 16, Bsrc + (tid + q * 256) * 4);
        asm volatile("cp.async.commit_group;");
    };

    fill(0, 0, va);

    for (int ch = 0; ch < 8; ch++) {
        const int s = ch & 1;
        if (ch < 7) {
            #pragma unroll
            for (int c = 0; c < 4; c++)
                va[c] = *reinterpret_cast<const float4*>(zsrc + (ch + 1) * 32 + c * 4);
        }
        asm volatile("cp.async.wait_group 0;" ::: "memory");
        __syncthreads();
        if (ch < 7) fill(ch + 1, s ^ 1, va);

        const uint2* A2 = reinterpret_cast<const uint2*>(sm + s * 32768);
        const uint2* B2 = reinterpret_cast<const uint2*>(sm + s * 32768 + 16384);
        #pragma unroll
        for (int ki = 0; ki < 4; ki++) {
            uint2 bf[4];
            #pragma unroll
            for (int j = 0; j < 4; j++)
                bf[j] = B2[((wn * 4 + j) * 4 + ki) * 32 + lane];
            #pragma unroll
            for (int m = 0; m < 4; m++) {
                int bm = wm * 4 + m;
                uint2 a01 = A2[(bm * 8 + 2 * ki) * 32 + lane];
                uint2 a23 = A2[(bm * 8 + 2 * ki + 1) * 32 + lane];
                #pragma unroll
                for (int j = 0; j < 4; j++)
                    mma_tf32(C[m][j], a01.x, a01.y, a23.x, a23.y, bf[j].x, bf[j].y);
            }
        }
    }
    __syncthreads();

    // epilogue: c = wsq - 2*dot; store fp16; per-row min
    float* smin = reinterpret_cast<float*>(sm + 65536);
    #pragma unroll
    for (int m = 0; m < 4; m++) {
        int r0 = wm * 64 + 16 * m + g;
        float mn0 = 1e30f, mn1 = 1e30f;
        #pragma unroll
        for (int j = 0; j < 4; j++) {
            int col = c0 + wn * 32 + j * 8 + 2 * tig;
            float w0 = g_wsq[col], w1 = g_wsq[col + 1];
            float s00 = fmaf(-2.f, C[m][j][0], w0);
            float s01 = fmaf(-2.f, C[m][j][1], w1);
            float s10 = fmaf(-2.f, C[m][j][2], w0);
            float s11 = fmaf(-2.f, C[m][j][3], w1);
            *reinterpret_cast<__half2*>(&g_scr[(size_t)(n0 + r0) * K_CODES + col]) =
                __floats2half2_rn(s00, s01);
            *reinterpret_cast<__half2*>(&g_scr[(size_t)(n0 + r0 + 8) * K_CODES + col]) =
                __floats2half2_rn(s10, s11);
            mn0 = fminf(mn0, fminf(s00, s01));
            mn1 = fminf(mn1, fminf(s10, s11));
        }
        #pragma unroll
        for (int o = 1; o < 4; o <<= 1) {
            mn0 = fminf(mn0, __shfl_xor_sync(0xffffffffu, mn0, o));
            mn1 = fminf(mn1, __shfl_xor_sync(0xffffffffu, mn1, o));
        }
        if (tig == 0) {
            smin[r0 * 4 + wn] = mn0;
            smin[(r0 + 8) * 4 + wn] = mn1;
        }
    }
    __syncthreads();
    if (tid < 128) {
        float v = fminf(fminf(smin[tid * 4], smin[tid * 4 + 1]),
                        fminf(smin[tid * 4 + 2], smin[tid * 4 + 3]));
        g_pval[(size_t)(n0 + tid) * 8 + blockIdx.y] = v;
    }
}

// ---------------- kernel 5: combine screen mins ----------------
__global__ void combine_kernel() {
    int n = blockIdx.x * 256 + threadIdx.x;
    float v = g_pval[(size_t)n * 8];
    #pragma unroll
    for (int t = 1; t < 8; t++) v = fminf(v, g_pval[(size_t)n * 8 + t]);
    g_cmin[n] = v;
}

// ---------------- kernel 6: exact rescore of candidates ----------------
__global__ void __launch_bounds__(256) rescore_kernel(const float* __restrict__ z) {
    int wid = threadIdx.x >> 5, lane = threadIdx.x & 31;
    int n = blockIdx.x * 8 + wid;
    float thr = g_cmin[n] + MARGIN;
    float sz = g_sumz[n];

    float zr[8];
    #pragma unroll
    for (int j = 0; j < 8; j++) zr[j] = z[(size_t)n * D_DIM + lane + 32 * j];

    float best = 1e30f; int besti = 0;
    const __half* crow = g_scr + (size_t)n * K_CODES;
    for (int ch = 0; ch < 32; ch++) {
        float cv = __half2float(crow[ch * 32 + lane]);
        unsigned bal = __ballot_sync(0xffffffffu, cv <= thr);
        while (bal) {
            int b = __ffs(bal) - 1;
            bal &= bal - 1;
            int k = ch * 32 + b;
            const float* wr = g_wT + (size_t)k * D_DIM;
            float acc = 0.f;
            #pragma unroll
            for (int j = 0; j < 8; j++) acc = fmaf(zr[j], wr[lane + 32 * j], acc);
            #pragma unroll
            for (int o = 16; o > 0; o >>= 1)
                acc += __shfl_down_sync(0xffffffffu, acc, o);
            if (lane == 0) {
                float t = sz + g_wsq[k];
                float dist = fmaf(-2.f, acc, t);
                if (dist < best) { best = dist; besti = k; }
            }
        }
    }
    if (lane == 0) g_closest[n] = besti;
}

// ---------------- kernel 7: gather + transpose + loss partials ----------------
__global__ void scatter_kernel(const float* __restrict__ z, float* __restrict__ out) {
    __shared__ int   sidx[32];
    __shared__ float tile[32][33];
    __shared__ float red[256];

    int n0 = blockIdx.x * 32, d0 = blockIdx.y * 32;
    int tid = threadIdx.x, warp = tid >> 5, lane = tid & 31;

    if (tid < 32) sidx[tid] = g_closest[n0 + tid];
    __syncthreads();

    float part = 0.f;
    #pragma unroll
    for (int it = 0; it < 4; it++) {
        int ni = it * 8 + warp;
        int n = n0 + ni;
        float zv = z[(size_t)n * D_DIM + d0 + lane];
        float q = g_wT[(size_t)sidx[ni] * D_DIM + d0 + lane];
        float d = q - zv;
        part = fmaf(d, d, part);
        tile[lane][ni] = zv + d;       // fl(z + fl(q - z)) matches ref ST
    }
    __syncthreads();

    int b = n0 >> 10;
    int hwbase = n0 & 1023;
    #pragma unroll
    for (int it = 0; it < 4; it++) {
        int dl = it * 8 + warp;
        out[(size_t)b * 262144 + (size_t)(d0 + dl) * 1024 + hwbase + lane] = tile[dl][lane];
    }

    red[tid] = part;
    __syncthreads();
    #pragma unroll
    for (int s = 128; s > 0; s >>= 1) {
        if (tid < s) red[tid] += red[tid + s];
        __syncthreads();
    }
    if (tid == 0) g_partial[blockIdx.y * 1024 + blockIdx.x] = red[0];
}

// ---------------- kernel 8: finalize losses ----------------
__global__ void finalize_kernel(float* __restrict__ out, int out_size) {
    __shared__ double sdata[256];
    int tid = threadIdx.x;
    double s = 0.0;
    for (int i = tid * 32; i < tid * 32 + 32; i++) s += (double)g_partial[i];
    sdata[tid] = s;
    __syncthreads();
    #pragma unroll
    for (int st = 128; st > 0; st >>= 1) {
        if (tid < st) sdata[tid] += sdata[tid + st];
        __syncthreads();
    }
    if (tid == 0) {
        float loss = (float)(sdata[0] / (double)OUT_ELEMS);
        out[out_size - 2] = loss;
        out[out_size - 1] = loss;
    }
}

// ---------------- launcher ----------------
extern "C" void kernel_launch(void* const* d_in, const int* in_sizes, int n_in,
                              void* d_out, int out_size) {
    (void)in_sizes; (void)n_in;
    const float* z = (const float*)d_in[0];
    const float* w = (const float*)d_in[1];
    float* out = (float*)d_out;

    static int inited = 0;
    if (!inited) {
        cudaFuncSetAttribute(screen_kernel, cudaFuncAttributeMaxDynamicSharedMemorySize, SCR_SMEM);
        inited = 1;
    }

    wsq_kernel<<<K_CODES / 256, 256>>>(w);
    splitw_kernel<<<dim3(K_CODES / 32, D_DIM / 32), dim3(32, 8)>>>(w);
    sumz_kernel<<<N_ROWS / 8, 256>>>(z);
    screen_kernel<<<dim3(N_ROWS / 128, K_CODES / 128), 256, SCR_SMEM>>>(z);
    combine_kernel<<<N_ROWS / 256, 256>>>();
    rescore_kernel<<<N_ROWS / 8, 256>>>(z);
    scatter_kernel<<<dim3(N_ROWS / 32, D_DIM / 32), 256>>>(z, out);
    finalize_kernel<<<1, 256>>>(out, out_size);
}

// round 5
// speedup vs baseline: 2.2772x; 1.5781x over previous
#include <cuda_runtime.h>
#include <cuda_fp16.h>
#include <cstdint>

#define N_ROWS   32768
#define D_DIM    256
#define K_CODES  1024
#define OUT_ELEMS 8388608
#define MARGIN   4e-3f

// ---------------- device scratch ----------------
__device__ float  g_wsq[K_CODES];
__device__ float  g_wT[K_CODES * D_DIM];           // exact fp32 transpose (rescore + gather)
__device__ __half g_wBpk[8][8][4096];              // fp16 prepacked B image [codeTile][dChunk]
__device__ float  g_sumz[N_ROWS];
__device__ float  g_pval[N_ROWS * 8];              // per-col-tile screen min
__device__ float  g_cmin[N_ROWS];
__device__ __half g_scr[(size_t)N_ROWS * K_CODES]; // screen values c = wsq - 2*dot
__device__ int    g_closest[N_ROWS];
__device__ float  g_partial[8192];

// ---------------- helpers ----------------
__device__ __forceinline__ uint32_t smem_u32(const void* p) {
    uint32_t a;
    asm("{ .reg .u64 t; cvta.to.shared.u64 t, %1; cvt.u32.u64 %0, t; }" : "=r"(a) : "l"(p));
    return a;
}
__device__ __forceinline__ uint32_t f2h2(float a, float b) {
    __half2 h = __floats2half2_rn(a, b);
    return *reinterpret_cast<uint32_t*>(&h);
}
__device__ __forceinline__ void cpasync16(uint32_t dst, const void* src) {
    asm volatile("cp.async.cg.shared.global [%0], [%1], 16;" :: "r"(dst), "l"(src));
}
__device__ __forceinline__ void mma_f16(float* c, uint32_t a0, uint32_t a1, uint32_t a2, uint32_t a3,
                                        uint32_t b0, uint32_t b1) {
    asm volatile(
        "mma.sync.aligned.m16n8k16.row.col.f32.f16.f16.f32 "
        "{%0,%1,%2,%3}, {%4,%5,%6,%7}, {%8,%9}, {%0,%1,%2,%3};"
        : "+f"(c[0]), "+f"(c[1]), "+f"(c[2]), "+f"(c[3])
        : "r"(a0), "r"(a1), "r"(a2), "r"(a3), "r"(b0), "r"(b1));
}

// ---------------- kernel 1: wsq ----------------
__global__ void wsq_kernel(const float* __restrict__ w) {
    int k = blockIdx.x * 256 + threadIdx.x;
    float s = 0.f;
    #pragma unroll 8
    for (int d = 0; d < D_DIM; d++) {
        float v = w[d * K_CODES + k];
        s = fmaf(v, v, s);
    }
    g_wsq[k] = s;
}

// ---------------- kernel 2: transpose + fp16 prepack of w ----------------
// B image per (ct, ch): uint2 idx = (kg*16 + nb)*32 + lane, lane = g*4+tig,
// halves within uint2: [k=2tig, 2tig+1, 2tig+8, 2tig+9] (k within 16-group), n = nb*8+g
__global__ void splitw_kernel(const float* __restrict__ w) {
    __shared__ float t[32][33];
    int k0 = blockIdx.x * 32, d0 = blockIdx.y * 32;   // grid (32, 8), block (32, 8)
    int x = threadIdx.x, y = threadIdx.y;
    #pragma unroll
    for (int i = 0; i < 32; i += 8)
        t[y + i][x] = w[(d0 + y + i) * K_CODES + k0 + x];
    __syncthreads();
    #pragma unroll
    for (int i = 0; i < 32; i += 8) {
        float v = t[x][y + i];
        int code = k0 + y + i, d = d0 + x;
        g_wT[code * D_DIM + d] = v;
        int ct = code >> 7, n = code & 127, ch = d >> 5, kw = d & 31;
        int kg = kw >> 4, ko = kw & 15;
        int tig = (ko & 7) >> 1, pp = ko & 1, hi = (ko >> 3) & 1;
        int g = n & 7, nb = n >> 3;
        int u2idx = (kg * 16 + nb) * 32 + g * 4 + tig;
        g_wBpk[ct][ch][u2idx * 4 + hi * 2 + pp] = __float2half(v);
    }
}

// ---------------- kernel 3: sumz ----------------
__global__ void sumz_kernel(const float* __restrict__ z) {
    int warp = threadIdx.x >> 5, lane = threadIdx.x & 31;
    int row = blockIdx.x * 8 + warp;
    const float* zr = z + (size_t)row * D_DIM;
    float s = 0.f;
    #pragma unroll
    for (int j = 0; j < D_DIM / 32; j++) {
        float v = zr[lane + 32 * j];
        s = fmaf(v, v, s);
    }
    #pragma unroll
    for (int o = 16; o > 0; o >>= 1)
        s += __shfl_down_sync(0xffffffffu, s, o);
    if (lane == 0) g_sumz[row] = s;
}

// ---------------- kernel 4: fp16 mma.sync screen GEMM ----------------
// grid (256, 8), 8 warps (2m x 4n), warp tile 64x32, BK=32, double buffered.
// SMEM per stage: A 8KB + B 8KB. A layout: uint4 idx = (b*2+kg)*32 + g*4 + tig,
// swizzled idx ^ ((idx>>5)&7); uint4 = {a0,a1,a2,a3} of m16n8k16.
#define SCR_SMEM (2 * 16384 + 2048)

__global__ void __launch_bounds__(256) screen_kernel(const float* __restrict__ z) {
    extern __shared__ char sm[];
    const uint32_t sb = smem_u32(sm);
    const int tid = threadIdx.x, wid = tid >> 5, lane = tid & 31;
    const int g = lane >> 2, tig = lane & 3;
    const int n0 = blockIdx.x * 128, c0 = blockIdx.y * 128;
    const int wm = wid & 1;            // m half (x64)
    const int wn = wid >> 1;           // n slab (x32)

    float C[4][4][4];
    #pragma unroll
    for (int m = 0; m < 4; m++)
        #pragma unroll
        for (int j = 0; j < 4; j++)
            #pragma unroll
            for (int q = 0; q < 4; q++) C[m][j][q] = 0.f;

    // A writer mapping: tid = bw*32 + gp*4 + kgw*2 + tp
    const int tp = tid & 1, kgw = (tid >> 1) & 1, gp = (tid >> 2) & 7, bw = tid >> 5;
    const float* zr0 = z + (size_t)(n0 + bw * 16 + gp) * D_DIM + kgw * 16 + tp * 4;
    const float* zr1 = zr0 + 8 * D_DIM;

    float4 va[4];
    va[0] = *reinterpret_cast<const float4*>(zr0);
    va[1] = *reinterpret_cast<const float4*>(zr0 + 8);
    va[2] = *reinterpret_cast<const float4*>(zr1);
    va[3] = *reinterpret_cast<const float4*>(zr1 + 8);

    auto fill = [&](int ch, int s, float4* v) {
        uint4* A4 = reinterpret_cast<uint4*>(sm + s * 16384);
        uint4 u0, u1;
        u0.x = f2h2(v[0].x, v[0].y); u0.y = f2h2(v[2].x, v[2].y);
        u0.z = f2h2(v[1].x, v[1].y); u0.w = f2h2(v[3].x, v[3].y);
        u1.x = f2h2(v[0].z, v[0].w); u1.y = f2h2(v[2].z, v[2].w);
        u1.z = f2h2(v[1].z, v[1].w); u1.w = f2h2(v[3].z, v[3].w);
        int idx0 = (bw * 2 + kgw) * 32 + gp * 4 + 2 * tp;
        A4[idx0 ^ ((idx0 >> 5) & 7)] = u0;
        int idx1 = idx0 + 1;
        A4[idx1 ^ ((idx1 >> 5) & 7)] = u1;
        // B: 8KB via cp.async
        uint32_t Bdst = sb + s * 16384 + 8192;
        const char* Bsrc = reinterpret_cast<const char*>(&g_wBpk[blockIdx.y][ch][0]);
        cpasync16(Bdst + tid * 16, Bsrc + tid * 16);
        cpasync16(Bdst + (tid + 256) * 16, Bsrc + (tid + 256) * 16);
        asm volatile("cp.async.commit_group;");
    };

    fill(0, 0, va);

    for (int ch = 0; ch < 8; ch++) {
        const int s = ch & 1;
        if (ch < 7) {
            va[0] = *reinterpret_cast<const float4*>(zr0 + (ch + 1) * 32);
            va[1] = *reinterpret_cast<const float4*>(zr0 + (ch + 1) * 32 + 8);
            va[2] = *reinterpret_cast<const float4*>(zr1 + (ch + 1) * 32);
            va[3] = *reinterpret_cast<const float4*>(zr1 + (ch + 1) * 32 + 8);
        }
        asm volatile("cp.async.wait_group 0;" ::: "memory");
        __syncthreads();
        if (ch < 7) fill(ch + 1, s ^ 1, va);

        const uint4* A4 = reinterpret_cast<const uint4*>(sm + s * 16384);
        const uint2* B2 = reinterpret_cast<const uint2*>(sm + s * 16384 + 8192);
        #pragma unroll
        for (int kg = 0; kg < 2; kg++) {
            uint2 bf[4];
            #pragma unroll
            for (int j = 0; j < 4; j++)
                bf[j] = B2[(kg * 16 + wn * 4 + j) * 32 + lane];
            #pragma unroll
            for (int m = 0; m < 4; m++) {
                int idx = ((wm * 4 + m) * 2 + kg) * 32 + lane;
                uint4 a = A4[idx ^ ((idx >> 5) & 7)];
                #pragma unroll
                for (int j = 0; j < 4; j++)
                    mma_f16(C[m][j], a.x, a.y, a.z, a.w, bf[j].x, bf[j].y);
            }
        }
    }
    __syncthreads();

    // epilogue: c = wsq - 2*dot; store fp16; per-row min
    float* smin = reinterpret_cast<float*>(sm + 32768);
    #pragma unroll
    for (int m = 0; m < 4; m++) {
        int r0 = wm * 64 + 16 * m + g;
        float mn0 = 1e30f, mn1 = 1e30f;
        #pragma unroll
        for (int j = 0; j < 4; j++) {
            int col = c0 + wn * 32 + j * 8 + 2 * tig;
            float w0 = g_wsq[col], w1 = g_wsq[col + 1];
            float s00 = fmaf(-2.f, C[m][j][0], w0);
            float s01 = fmaf(-2.f, C[m][j][1], w1);
            float s10 = fmaf(-2.f, C[m][j][2], w0);
            float s11 = fmaf(-2.f, C[m][j][3], w1);
            *reinterpret_cast<__half2*>(&g_scr[(size_t)(n0 + r0) * K_CODES + col]) =
                __floats2half2_rn(s00, s01);
            *reinterpret_cast<__half2*>(&g_scr[(size_t)(n0 + r0 + 8) * K_CODES + col]) =
                __floats2half2_rn(s10, s11);
            mn0 = fminf(mn0, fminf(s00, s01));
            mn1 = fminf(mn1, fminf(s10, s11));
        }
        #pragma unroll
        for (int o = 1; o < 4; o <<= 1) {
            mn0 = fminf(mn0, __shfl_xor_sync(0xffffffffu, mn0, o));
            mn1 = fminf(mn1, __shfl_xor_sync(0xffffffffu, mn1, o));
        }
        if (tig == 0) {
            smin[r0 * 4 + wn] = mn0;
            smin[(r0 + 8) * 4 + wn] = mn1;
        }
    }
    __syncthreads();
    if (tid < 128) {
        float v = fminf(fminf(smin[tid * 4], smin[tid * 4 + 1]),
                        fminf(smin[tid * 4 + 2], smin[tid * 4 + 3]));
        g_pval[(size_t)(n0 + tid) * 8 + blockIdx.y] = v;
    }
}

// ---------------- kernel 5: combine screen mins ----------------
__global__ void combine_kernel() {
    int n = blockIdx.x * 256 + threadIdx.x;
    float v = g_pval[(size_t)n * 8];
    #pragma unroll
    for (int t = 1; t < 8; t++) v = fminf(v, g_pval[(size_t)n * 8 + t]);
    g_cmin[n] = v;
}

// ---------------- kernel 6: exact rescore of candidates ----------------
__global__ void __launch_bounds__(256) rescore_kernel(const float* __restrict__ z) {
    int wid = threadIdx.x >> 5, lane = threadIdx.x & 31;
    int n = blockIdx.x * 8 + wid;
    float thr = g_cmin[n] + MARGIN;
    float sz = g_sumz[n];

    float zr[8];
    #pragma unroll
    for (int j = 0; j < 8; j++) zr[j] = z[(size_t)n * D_DIM + lane + 32 * j];

    float best = 1e30f; int besti = 0;
    const uint4* crow = reinterpret_cast<const uint4*>(g_scr + (size_t)n * K_CODES);
    #pragma unroll
    for (int q = 0; q < 4; q++) {
        uint4 v = crow[q * 32 + lane];
        const __half2* hp = reinterpret_cast<const __half2*>(&v);
        unsigned m8 = 0;
        #pragma unroll
        for (int e = 0; e < 4; e++) {
            float lo = __low2float(hp[e]), hi = __high2float(hp[e]);
            if (lo <= thr) m8 |= 1u << (2 * e);
            if (hi <= thr) m8 |= 1u << (2 * e + 1);
        }
        unsigned bal = __ballot_sync(0xffffffffu, m8 != 0);
        while (bal) {
            int src = __ffs(bal) - 1;
            bal &= bal - 1;
            unsigned mm = __shfl_sync(0xffffffffu, m8, src);
            while (mm) {
                int bit = __ffs(mm) - 1;
                mm &= mm - 1;
                int k = (q * 32 + src) * 8 + bit;
                const float* wr = g_wT + (size_t)k * D_DIM;
                float acc = 0.f;
                #pragma unroll
                for (int j = 0; j < 8; j++) acc = fmaf(zr[j], wr[lane + 32 * j], acc);
                #pragma unroll
                for (int o = 16; o > 0; o >>= 1)
                    acc += __shfl_down_sync(0xffffffffu, acc, o);
                if (lane == 0) {
                    float t = sz + g_wsq[k];
                    float dist = fmaf(-2.f, acc, t);
                    if (dist < best) { best = dist; besti = k; }  // ascending k -> first wins ties
                }
            }
        }
    }
    if (lane == 0) g_closest[n] = besti;
}

// ---------------- kernel 7: gather + transpose + loss partials ----------------
__global__ void scatter_kernel(const float* __restrict__ z, float* __restrict__ out) {
    __shared__ int   sidx[32];
    __shared__ float tile[32][33];
    __shared__ float red[256];

    int n0 = blockIdx.x * 32, d0 = blockIdx.y * 32;
    int tid = threadIdx.x, warp = tid >> 5, lane = tid & 31;

    if (tid < 32) sidx[tid] = g_closest[n0 + tid];
    __syncthreads();

    float part = 0.f;
    #pragma unroll
    for (int it = 0; it < 4; it++) {
        int ni = it * 8 + warp;
        int n = n0 + ni;
        float zv = z[(size_t)n * D_DIM + d0 + lane];
        float q = g_wT[(size_t)sidx[ni] * D_DIM + d0 + lane];
        float d = q - zv;
        part = fmaf(d, d, part);
        tile[lane][ni] = zv + d;       // fl(z + fl(q - z)) matches ref ST
    }
    __syncthreads();

    int b = n0 >> 10;
    int hwbase = n0 & 1023;
    #pragma unroll
    for (int it = 0; it < 4; it++) {
        int dl = it * 8 + warp;
        out[(size_t)b * 262144 + (size_t)(d0 + dl) * 1024 + hwbase + lane] = tile[dl][lane];
    }

    red[tid] = part;
    __syncthreads();
    #pragma unroll
    for (int s = 128; s > 0; s >>= 1) {
        if (tid < s) red[tid] += red[tid + s];
        __syncthreads();
    }
    if (tid == 0) g_partial[blockIdx.y * 1024 + blockIdx.x] = red[0];
}

// ---------------- kernel 8: finalize losses ----------------
__global__ void finalize_kernel(float* __restrict__ out, int out_size) {
    __shared__ double sdata[256];
    int tid = threadIdx.x;
    double s = 0.0;
    for (int i = tid * 32; i < tid * 32 + 32; i++) s += (double)g_partial[i];
    sdata[tid] = s;
    __syncthreads();
    #pragma unroll
    for (int st = 128; st > 0; st >>= 1) {
        if (tid < st) sdata[tid] += sdata[tid + st];
        __syncthreads();
    }
    if (tid == 0) {
        float loss = (float)(sdata[0] / (double)OUT_ELEMS);
        out[out_size - 2] = loss;
        out[out_size - 1] = loss;
    }
}

// ---------------- launcher ----------------
extern "C" void kernel_launch(void* const* d_in, const int* in_sizes, int n_in,
                              void* d_out, int out_size) {
    (void)in_sizes; (void)n_in;
    const float* z = (const float*)d_in[0];
    const float* w = (const float*)d_in[1];
    float* out = (float*)d_out;

    wsq_kernel<<<K_CODES / 256, 256>>>(w);
    splitw_kernel<<<dim3(K_CODES / 32, D_DIM / 32), dim3(32, 8)>>>(w);
    sumz_kernel<<<N_ROWS / 8, 256>>>(z);
    screen_kernel<<<dim3(N_ROWS / 128, K_CODES / 128), 256, SCR_SMEM>>>(z);
    combine_kernel<<<N_ROWS / 256, 256>>>();
    rescore_kernel<<<N_ROWS / 8, 256>>>(z);
    scatter_kernel<<<dim3(N_ROWS / 32, D_DIM / 32), 256>>>(z, out);
    finalize_kernel<<<1, 256>>>(out, out_size);
}